// round 8
// baseline (speedup 1.0000x reference)
#include <cuda_runtime.h>
#include <cuda_fp16.h>
#include <cstdint>

#define DIN 1024
#define HD  128
#define BM  128
#define KC  32
#define NCHUNK (DIN/KC)   // 32

// ---------------- preconverted weights (transposed, single fp16) -----------
__device__ __half g_W0T[HD*DIN];
__device__ __half g_W1T[HD*HD];
__device__ __half g_W2T[HD*HD];

// WT[n][k] = fp16(W[k][n])
__global__ void prep_w(const float* __restrict__ W, int K, int which)
{
    __shared__ float t[32][33];
    __half* dst = which==0 ? g_W0T : (which==1 ? g_W1T : g_W2T);
    int bx = blockIdx.x, by = blockIdx.y;
    int tx = threadIdx.x, ty = threadIdx.y;   // (32,8)
    #pragma unroll
    for (int r = 0; r < 32; r += 8)
        t[ty+r][tx] = W[(size_t)(bx*32 + ty + r)*HD + by*32 + tx];
    __syncthreads();
    #pragma unroll
    for (int r = 0; r < 32; r += 8) {
        int n = by*32 + ty + r;
        int k = bx*32 + tx;
        dst[(size_t)n*K + k] = __float2half_rn(t[tx][ty+r]);
    }
}

// ---------------- helpers ---------------------------------------------------
__device__ __forceinline__ uint32_t smem_u32(const void* p) {
    uint32_t a;
    asm("{ .reg .u64 t; cvta.to.shared.u64 t, %1; cvt.u32.u64 %0, t; }" : "=r"(a) : "l"(p));
    return a;
}
__device__ __forceinline__ uint32_t sw128(uint32_t o) { return o ^ ((o >> 3) & 0x70); }
__device__ __forceinline__ uint32_t sw512(uint32_t o) { return o ^ ((o >> 5) & 0x70); }

__device__ __forceinline__ void cpasync16(uint32_t dst, const void* src) {
    asm volatile("cp.async.cg.shared.global [%0], [%1], 16;" :: "r"(dst), "l"(src));
}
#define CP_COMMIT()  asm volatile("cp.async.commit_group;" ::: "memory")
#define CP_WAIT0()   asm volatile("cp.async.wait_group 0;"  ::: "memory")
#define CP_WAIT1()   asm volatile("cp.async.wait_group 1;"  ::: "memory")

__device__ __forceinline__ void ldsm4(uint32_t addr, uint32_t* r) {
    asm volatile("ldmatrix.sync.aligned.m8n8.x4.shared.b16 {%0,%1,%2,%3}, [%4];"
        : "=r"(r[0]), "=r"(r[1]), "=r"(r[2]), "=r"(r[3]) : "r"(addr));
}
__device__ __forceinline__ void mma16816(float* c, const uint32_t* a, uint32_t b0, uint32_t b1) {
    asm volatile("mma.sync.aligned.m16n8k16.row.col.f32.f16.f16.f32 "
        "{%0,%1,%2,%3}, {%4,%5,%6,%7}, {%8,%9}, {%0,%1,%2,%3};"
        : "+f"(c[0]), "+f"(c[1]), "+f"(c[2]), "+f"(c[3])
        : "r"(a[0]), "r"(a[1]), "r"(a[2]), "r"(a[3]), "r"(b0), "r"(b1));
}

// ---------------- smem layout (same as round 7; 2 CTAs/SM) ------------------
// GEMM0 stages: 2 x 32KB at [0, 64K). Stage: A(128 rows x [32hi|32lo] fp16
//   = 128B row) at +0 (16KB), B(128 n-rows x 128B row, only first 64B = 32
//   fp16 used) at +16K (16KB).
// After GEMM0 the same 64KB holds h: 128 rows x [256B hi | 256B lo] = 512B.
// W quarters: 2 x 16KB double buffer at [64K, 96K); only first 64B/row used.
#define STG0   0
#define STG1   32768
#define A_OFF  0
#define B_OFF  16384
#define WQ0    65536
#define WQ1    81920
#define S_BIAS 98304
#define S_PART 99840
#define SMEM_TOTAL 100864

__global__ __launch_bounds__(256, 2)
void fused_mlp_mma(const float* __restrict__ x,
                   const float* __restrict__ b0,
                   const float* __restrict__ b1,
                   const float* __restrict__ b2,
                   float* __restrict__ out)
{
    extern __shared__ char smem[];
    const uint32_t su = smem_u32(smem);
    const int tid  = threadIdx.x;
    const int lane = tid & 31;
    const int wid  = tid >> 5;           // 8 warps: 4 in M x 2 in N
    const int wm   = wid & 3;
    const int wn   = wid >> 2;
    const int m0   = blockIdx.x * BM;

    float* b0s = (float*)(smem + S_BIAS);
    float* b1s = (float*)(smem + S_BIAS + 512);
    float* b2s = (float*)(smem + S_BIAS + 1024);
    float* part = (float*)(smem + S_PART);      // [2][128]
    if (tid < HD) { b0s[tid] = b0[tid]; b1s[tid] = b1[tid]; b2s[tid] = b2[tid]; }

    const uint32_t aLane   = (uint32_t)(lane & 15);
    const uint32_t aColSel = (uint32_t)((lane >> 4) * 16);
    const uint32_t bRow    = (uint32_t)((lane & 7) + ((lane >> 4) & 1) * 8);
    const uint32_t bColSel = (uint32_t)(((lane >> 3) & 1) * 16);
    const int colbase = (lane & 3) * 2;
    const int qr = lane >> 2;

    float acc[2][8][4];
    auto zero_acc = [&]() {
        #pragma unroll
        for (int a = 0; a < 2; a++)
            #pragma unroll
            for (int n = 0; n < 8; n++)
                #pragma unroll
                for (int q = 0; q < 4; q++) acc[a][n][q] = 0.f;
    };
    zero_acc();

    // inner MMA step: A hi/lo frags (2-pass), B single fp16 from bbase
    auto gemm_step = [&](const uint32_t* aHi, const uint32_t* aLo,
                         uint32_t bbase, uint32_t bks) {
        uint32_t ah[2][4], al[2][4];
        ldsm4(aHi[0], ah[0]); ldsm4(aLo[0], al[0]);
        ldsm4(aHi[1], ah[1]); ldsm4(aLo[1], al[1]);
        #pragma unroll
        for (int nn = 0; nn < 4; nn++) {
            uint32_t ob = (uint32_t)(wn*64 + nn*16 + bRow) * 128 + bks + bColSel;
            uint32_t bh[4];
            ldsm4(bbase + sw128(ob), bh);
            #pragma unroll
            for (int mi = 0; mi < 2; mi++) {
                mma16816(acc[mi][nn*2],   ah[mi], bh[0], bh[1]);
                mma16816(acc[mi][nn*2],   al[mi], bh[0], bh[1]);
                mma16816(acc[mi][nn*2+1], ah[mi], bh[2], bh[3]);
                mma16816(acc[mi][nn*2+1], al[mi], bh[2], bh[3]);
            }
        }
    };

    // ---- loaders ----
    float4 xr[4];
    auto load_x = [&](int chunk) {
        const float* xb = x + (size_t)m0 * DIN + chunk * KC;
        #pragma unroll
        for (int j = 0; j < 4; j++) {
            int flat = j * 256 + tid;            // 0..1023
            int row = flat >> 3, c4 = flat & 7;
            xr[j] = *(const float4*)(xb + (size_t)row * DIN + c4 * 4);
        }
    };
    auto sts_A = [&](uint32_t sb) {
        #pragma unroll
        for (int j = 0; j < 4; j++) {
            int flat = j * 256 + tid;
            int row = flat >> 3, c4 = flat & 7;
            float4 f = xr[j];
            __half2 h01 = __floats2half2_rn(f.x, f.y);
            __half2 h23 = __floats2half2_rn(f.z, f.w);
            __half2 l01 = __floats2half2_rn(f.x - __low2float(h01), f.y - __high2float(h01));
            __half2 l23 = __floats2half2_rn(f.z - __low2float(h23), f.w - __high2float(h23));
            uint2 hv = { *(uint32_t*)&h01, *(uint32_t*)&h23 };
            uint2 lv = { *(uint32_t*)&l01, *(uint32_t*)&l23 };
            *(uint2*)(smem + sb + A_OFF + sw128((uint32_t)(row*128 + c4*8)))      = hv;
            *(uint2*)(smem + sb + A_OFF + sw128((uint32_t)(row*128 + 64 + c4*8))) = lv;
        }
    };
    auto cp_B = [&](int chunk, uint32_t sb) {
        const int k0 = chunk * KC;
        #pragma unroll
        for (int j = 0; j < 2; j++) {
            int flat = j * 256 + tid;            // 0..511
            int row = flat >> 2, g = flat & 3;
            cpasync16(su + sb + B_OFF + sw128((uint32_t)(row*128 + g*16)),
                      g_W0T + (size_t)row * DIN + k0 + g*8);
        }
    };
    auto cp_Wq = [&](const __half* src, int kq, uint32_t buf) {
        const int k0 = kq * 32;
        #pragma unroll
        for (int j = 0; j < 2; j++) {
            int flat = j * 256 + tid;
            int row = flat >> 2, g = flat & 3;
            cpasync16(su + buf + sw128((uint32_t)(row*128 + g*16)),
                      src + (size_t)row * HD + k0 + g*8);
        }
    };

    auto compute_chunk0 = [&](uint32_t sb) {
        #pragma unroll
        for (int ks = 0; ks < 2; ks++) {
            uint32_t aHi[2], aLo[2];
            #pragma unroll
            for (int mi = 0; mi < 2; mi++) {
                uint32_t oa = (uint32_t)(wm*32 + mi*16 + aLane) * 128 + (uint32_t)ks*32 + aColSel;
                aHi[mi] = su + sb + A_OFF + sw128(oa);
                aLo[mi] = su + sb + A_OFF + sw128(oa + 64);
            }
            gemm_step(aHi, aLo, su + sb + B_OFF, (uint32_t)ks*32);
        }
    };
    auto compute_q = [&](uint32_t kbase, uint32_t wbuf) {
        #pragma unroll
        for (int ks = 0; ks < 2; ks++) {
            uint32_t aHi[2], aLo[2];
            #pragma unroll
            for (int mi = 0; mi < 2; mi++) {
                uint32_t oa = (uint32_t)(wm*32 + mi*16 + aLane) * 512 + kbase + (uint32_t)ks*32 + aColSel;
                aHi[mi] = su + sw512(oa);
                aLo[mi] = su + sw512(oa + 256);
            }
            gemm_step(aHi, aLo, su + wbuf, (uint32_t)ks*32);
        }
    };

    // ---- GEMM0 mainloop: 2-stage ring --------------------------------------
    load_x(0);
    cp_B(0, STG0); CP_COMMIT();
    sts_A(STG0);
    load_x(1);
    CP_WAIT0();
    __syncthreads();

    for (int i = 0; i < NCHUNK; i++) {
        const uint32_t sb  = (i & 1) ? STG1 : STG0;
        const uint32_t sbn = (i & 1) ? STG0 : STG1;
        if (i < NCHUNK - 1) {
            cp_B(i + 1, sbn); CP_COMMIT();
            sts_A(sbn);                           // xr holds chunk i+1
            if (i < NCHUNK - 2) load_x(i + 2);
        }
        compute_chunk0(sb);
        if (i < NCHUNK - 1) {
            CP_WAIT0();
            __syncthreads();
        }
    }
    __syncthreads();    // all warps done with stages (h will overwrite them)

    // ---- start W1 quarter stream (overlaps epilogue 0) ---------------------
    cp_Wq(g_W1T, 0, WQ0); CP_COMMIT();
    cp_Wq(g_W1T, 1, WQ1); CP_COMMIT();

    // ---- epilogue 0: bias + rmsnorm; h -> packed smem (512B rows) ----------
    {
        float ssp[4] = {0.f, 0.f, 0.f, 0.f};
        #pragma unroll
        for (int mi = 0; mi < 2; mi++)
            #pragma unroll
            for (int nn = 0; nn < 4; nn++)
                #pragma unroll
                for (int p = 0; p < 2; p++) {
                    float2 bv = *(float2*)&b0s[wn*64 + nn*16 + p*8 + colbase];
                    float* c = acc[mi][nn*2 + p];
                    c[0] += bv.x; c[1] += bv.y; c[2] += bv.x; c[3] += bv.y;
                    ssp[mi*2]     = fmaf(c[0], c[0], fmaf(c[1], c[1], ssp[mi*2]));
                    ssp[mi*2 + 1] = fmaf(c[2], c[2], fmaf(c[3], c[3], ssp[mi*2 + 1]));
                }
        #pragma unroll
        for (int i = 0; i < 4; i++) {
            ssp[i] += __shfl_xor_sync(0xffffffffu, ssp[i], 1);
            ssp[i] += __shfl_xor_sync(0xffffffffu, ssp[i], 2);
        }
        if ((lane & 3) == 0) {
            #pragma unroll
            for (int i = 0; i < 4; i++)
                part[wn*128 + wm*32 + (i >> 1)*16 + (i & 1)*8 + qr] = ssp[i];
        }
        __syncthreads();
        #pragma unroll
        for (int i = 0; i < 4; i++) {
            int r = wm*32 + (i >> 1)*16 + (i & 1)*8 + qr;
            float sc = rsqrtf((part[r] + part[128 + r]) * (1.f/128.f) + 1e-6f);
            int mi = i >> 1, half = i & 1;
            #pragma unroll
            for (int nn = 0; nn < 4; nn++)
                #pragma unroll
                for (int p = 0; p < 2; p++) {
                    float v0 = acc[mi][nn*2 + p][half*2]     * sc;
                    float v1 = acc[mi][nn*2 + p][half*2 + 1] * sc;
                    __half2 h2 = __floats2half2_rn(v0, v1);
                    __half2 l2 = __floats2half2_rn(v0 - __low2float(h2), v1 - __high2float(h2));
                    uint32_t oo = (uint32_t)r * 512 + (uint32_t)(wn*64 + nn*16 + p*8 + colbase) * 2;
                    *(uint32_t*)(smem + sw512(oo))       = *(uint32_t*)&h2;
                    *(uint32_t*)(smem + sw512(oo + 256)) = *(uint32_t*)&l2;
                }
        }
    }
    CP_WAIT1();          // W1 quarter 0 arrived
    __syncthreads();     // h + WQ0 visible to all

    // ---- GEMM1: h @ W1, streamed in 4 k-quarters ---------------------------
    zero_acc();
    compute_q(0,   WQ0);
    __syncthreads();
    cp_Wq(g_W1T, 2, WQ0); CP_COMMIT();
    CP_WAIT1(); __syncthreads();
    compute_q(64,  WQ1);
    __syncthreads();
    cp_Wq(g_W1T, 3, WQ1); CP_COMMIT();
    CP_WAIT1(); __syncthreads();
    compute_q(128, WQ0);
    __syncthreads();
    cp_Wq(g_W2T, 0, WQ0); CP_COMMIT();
    CP_WAIT1(); __syncthreads();
    compute_q(192, WQ1);
    __syncthreads();     // all warps done reading h + WQ1
    cp_Wq(g_W2T, 1, WQ1); CP_COMMIT();

    // ---- epilogue 1: sigmoid + residual (from smem); rewrite h -------------
    #pragma unroll
    for (int mi = 0; mi < 2; mi++)
        #pragma unroll
        for (int half = 0; half < 2; half++) {
            int r = wm*32 + mi*16 + half*8 + qr;
            #pragma unroll
            for (int nn = 0; nn < 4; nn++)
                #pragma unroll
                for (int p = 0; p < 2; p++) {
                    int col = wn*64 + nn*16 + p*8 + colbase;
                    float2 bv = *(float2*)&b1s[col];
                    uint32_t oo = (uint32_t)r * 512 + (uint32_t)col * 2;
                    uint32_t hu = *(uint32_t*)(smem + sw512(oo));
                    uint32_t lu = *(uint32_t*)(smem + sw512(oo + 256));
                    __half2 hb = *(__half2*)&hu;
                    __half2 lb = *(__half2*)&lu;
                    float r0 = __low2float(hb)  + __low2float(lb);
                    float r1 = __high2float(hb) + __high2float(lb);
                    float v0 = 1.f / (1.f + __expf(-(acc[mi][nn*2+p][half*2]     + bv.x))) + r0;
                    float v1 = 1.f / (1.f + __expf(-(acc[mi][nn*2+p][half*2 + 1] + bv.y))) + r1;
                    __half2 h2 = __floats2half2_rn(v0, v1);
                    __half2 l2 = __floats2half2_rn(v0 - __low2float(h2), v1 - __high2float(h2));
                    *(uint32_t*)(smem + sw512(oo))       = *(uint32_t*)&h2;
                    *(uint32_t*)(smem + sw512(oo + 256)) = *(uint32_t*)&l2;
                }
        }
    CP_WAIT1();          // W2 quarter 0 arrived
    __syncthreads();     // new h + WQ0 visible

    // ---- GEMM2: h1 @ W2, streamed in 4 k-quarters --------------------------
    zero_acc();
    compute_q(0,   WQ0);
    __syncthreads();
    cp_Wq(g_W2T, 2, WQ0); CP_COMMIT();
    CP_WAIT1(); __syncthreads();
    compute_q(64,  WQ1);
    __syncthreads();
    cp_Wq(g_W2T, 3, WQ1); CP_COMMIT();
    CP_WAIT1(); __syncthreads();
    compute_q(128, WQ0);
    CP_WAIT0(); __syncthreads();
    compute_q(192, WQ1);

    // ---- epilogue 2: relu + residual (from smem); store ---------------------
    #pragma unroll
    for (int mi = 0; mi < 2; mi++)
        #pragma unroll
        for (int half = 0; half < 2; half++) {
            int r = wm*32 + mi*16 + half*8 + qr;
            float* orow = out + (size_t)(m0 + r) * HD;
            #pragma unroll
            for (int nn = 0; nn < 4; nn++)
                #pragma unroll
                for (int p = 0; p < 2; p++) {
                    int col = wn*64 + nn*16 + p*8 + colbase;
                    float2 bv = *(float2*)&b2s[col];
                    uint32_t oo = (uint32_t)r * 512 + (uint32_t)col * 2;
                    uint32_t hu = *(uint32_t*)(smem + sw512(oo));
                    uint32_t lu = *(uint32_t*)(smem + sw512(oo + 256));
                    __half2 hb = *(__half2*)&hu;
                    __half2 lb = *(__half2*)&lu;
                    float r0 = __low2float(hb)  + __low2float(lb);
                    float r1 = __high2float(hb) + __high2float(lb);
                    float2 o;
                    o.x = fmaxf(acc[mi][nn*2 + p][half*2]     + bv.x, 0.f) + r0;
                    o.y = fmaxf(acc[mi][nn*2 + p][half*2 + 1] + bv.y, 0.f) + r1;
                    *(float2*)(orow + col) = o;
                }
        }
}

// ---------------- launch ----------------------------------------------------
extern "C" void kernel_launch(void* const* d_in, const int* in_sizes, int n_in,
                              void* d_out, int out_size)
{
    const float* x  = (const float*)d_in[0];
    const float* W0 = (const float*)d_in[1];
    const float* b0 = (const float*)d_in[2];
    const float* W1 = (const float*)d_in[3];
    const float* b1 = (const float*)d_in[4];
    const float* W2 = (const float*)d_in[5];
    const float* b2 = (const float*)d_in[6];
    float* out = (float*)d_out;

    const int M = in_sizes[0] / DIN;   // 32768

    prep_w<<<dim3(DIN/32, HD/32), dim3(32, 8)>>>(W0, DIN, 0);
    prep_w<<<dim3(HD/32,  HD/32), dim3(32, 8)>>>(W1, HD, 1);
    prep_w<<<dim3(HD/32,  HD/32), dim3(32, 8)>>>(W2, HD, 2);

    cudaFuncSetAttribute(fused_mlp_mma,
                         cudaFuncAttributeMaxDynamicSharedMemorySize, SMEM_TOTAL);
    fused_mlp_mma<<<M / BM, 256, SMEM_TOTAL>>>(x, b0, b1, b2, out);
}

// round 12
// speedup vs baseline: 2.1439x; 2.1439x over previous
#include <cuda_runtime.h>
#include <cuda_fp16.h>
#include <cstdint>

#define DIN 1024
#define HD  128
#define BM  64
#define KC  32
#define NCHUNK (DIN/KC)   // 32
#define THREADS 256

// ---------------- preconverted weights (transposed, single fp16) -----------
__device__ __half g_W0T[HD*DIN];
__device__ __half g_W1T[HD*HD];
__device__ __half g_W2T[HD*HD];

// WT[n][k] = fp16(W[k][n])
__global__ void prep_w(const float* __restrict__ W, int K, int which)
{
    __shared__ float t[32][33];
    __half* dst = which==0 ? g_W0T : (which==1 ? g_W1T : g_W2T);
    int bx = blockIdx.x, by = blockIdx.y;
    int tx = threadIdx.x, ty = threadIdx.y;   // (32,8)
    #pragma unroll
    for (int r = 0; r < 32; r += 8)
        t[ty+r][tx] = W[(size_t)(bx*32 + ty + r)*HD + by*32 + tx];
    __syncthreads();
    #pragma unroll
    for (int r = 0; r < 32; r += 8) {
        int n = by*32 + ty + r;
        int k = bx*32 + tx;
        dst[(size_t)n*K + k] = __float2half_rn(t[tx][ty+r]);
    }
}

// ---------------- helpers ---------------------------------------------------
__device__ __forceinline__ uint32_t smem_u32(const void* p) {
    uint32_t a;
    asm("{ .reg .u64 t; cvta.to.shared.u64 t, %1; cvt.u32.u64 %0, t; }" : "=r"(a) : "l"(p));
    return a;
}
// swizzles: XOR row bits into 16B-bank bits [6:4]
__device__ __forceinline__ uint32_t sw64 (uint32_t o) { return o ^ ((o >> 3) & 0x30); } // 64B rows
__device__ __forceinline__ uint32_t sw128(uint32_t o) { return o ^ ((o >> 3) & 0x70); } // 128B rows
__device__ __forceinline__ uint32_t sw256(uint32_t o) { return o ^ ((o >> 4) & 0x70); } // 256B rows

__device__ __forceinline__ void cpasync16(uint32_t dst, const void* src) {
    asm volatile("cp.async.cg.shared.global [%0], [%1], 16;" :: "r"(dst), "l"(src));
}
#define CP_COMMIT()  asm volatile("cp.async.commit_group;" ::: "memory")
#define CP_WAIT0()   asm volatile("cp.async.wait_group 0;"  ::: "memory")
#define CP_WAIT1()   asm volatile("cp.async.wait_group 1;"  ::: "memory")
#define CP_WAIT2()   asm volatile("cp.async.wait_group 2;"  ::: "memory")

__device__ __forceinline__ void ldsm4(uint32_t addr, uint32_t* r) {
    asm volatile("ldmatrix.sync.aligned.m8n8.x4.shared.b16 {%0,%1,%2,%3}, [%4];"
        : "=r"(r[0]), "=r"(r[1]), "=r"(r[2]), "=r"(r[3]) : "r"(addr));
}
__device__ __forceinline__ void mma16816(float* c, const uint32_t* a, uint32_t b0, uint32_t b1) {
    asm volatile("mma.sync.aligned.m16n8k16.row.col.f32.f16.f16.f32 "
        "{%0,%1,%2,%3}, {%4,%5,%6,%7}, {%8,%9}, {%0,%1,%2,%3};"
        : "+f"(c[0]), "+f"(c[1]), "+f"(c[2]), "+f"(c[3])
        : "r"(a[0]), "r"(a[1]), "r"(a[2]), "r"(a[3]), "r"(b0), "r"(b1));
}

// ---------------- smem layout (74.5KB -> 3 CTAs/SM) -------------------------
// 4 stages x 16KB at [0,64K). Stage: x_f32 (64 rows x 128B, sw128) at +0,
//   B_f16 (128 n-rows x 64B, sw64) at +8K.
// A ring: 2 x 4KB at [64K,72K): 64 rows x 64B fp16, sw64.
// Phase 2 overlays [0,48K): h (64 rows x 256B fp16, sw256) at 0,
//   W half buffers WB0/WB1 (128 n-rows x 128B, sw128) at 16K/32K.
#define STG(s)  ((uint32_t)(s) * 16384u)
#define X_OFF   0
#define B_OFF   8192
#define A_RING  65536
#define H_OFF   0
#define WB0     16384
#define WB1     32768
#define S_BIAS  73728
#define S_PART  75264
#define SMEM_TOTAL 76288

__global__ __launch_bounds__(256, 3)
void fused_mlp_v9(const float* __restrict__ x,
                  const float* __restrict__ b0,
                  const float* __restrict__ b1,
                  const float* __restrict__ b2,
                  float* __restrict__ out)
{
    extern __shared__ char smem[];
    const uint32_t su = smem_u32(smem);
    const int tid  = threadIdx.x;
    const int lane = tid & 31;
    const int wid  = tid >> 5;       // 8 warps: 2 in M x 4 in N
    const int wm   = wid & 1;        // rows wm*32..+32
    const int wn   = wid >> 1;       // cols wn*32..+32
    const int m0   = blockIdx.x * BM;

    float* b0s = (float*)(smem + S_BIAS);
    float* b1s = (float*)(smem + S_BIAS + 512);
    float* b2s = (float*)(smem + S_BIAS + 1024);
    float* part = (float*)(smem + S_PART);   // [4][64]
    if (tid < HD) { b0s[tid] = b0[tid]; b1s[tid] = b1[tid]; b2s[tid] = b2[tid]; }

    const uint32_t aLane   = (uint32_t)(lane & 15);
    const uint32_t aColSel = (uint32_t)((lane >> 4) * 16);
    const uint32_t bRow    = (uint32_t)((lane & 7) + ((lane >> 4) & 1) * 8);
    const uint32_t bColSel = (uint32_t)(((lane >> 3) & 1) * 16);
    const int colbase = (lane & 3) * 2;
    const int qr = lane >> 2;

    float acc[2][4][4];
    auto zero_acc = [&]() {
        #pragma unroll
        for (int a = 0; a < 2; a++)
            #pragma unroll
            for (int n = 0; n < 4; n++)
                #pragma unroll
                for (int q = 0; q < 4; q++) acc[a][n][q] = 0.f;
    };
    zero_acc();

    // ---- async loaders ------------------------------------------------------
    auto cp_chunk = [&](int chunk) {
        uint32_t sb = STG(chunk & 3);
        const float* xb = x + (size_t)m0 * DIN + chunk * KC;
        #pragma unroll
        for (int j = 0; j < 2; j++) {
            int flat = j * 256 + tid;         // 0..511
            int row = flat >> 3, c = flat & 7;
            cpasync16(su + sb + X_OFF + sw128((uint32_t)(row*128 + c*16)),
                      xb + (size_t)row * DIN + c*4);
        }
        const __half* wb = g_W0T + chunk * KC;
        #pragma unroll
        for (int j = 0; j < 2; j++) {
            int flat = j * 256 + tid;         // 0..511
            int row = flat >> 2, g = flat & 3;
            cpasync16(su + sb + B_OFF + sw64((uint32_t)(row*64 + g*16)),
                      wb + (size_t)row * DIN + g*8);
        }
        CP_COMMIT();
    };
    auto cp_Whalf = [&](const __half* src, int half, uint32_t dstb) {
        #pragma unroll
        for (int j = 0; j < 4; j++) {
            int flat = j * 256 + tid;         // 0..1023
            int row = flat >> 3, g = flat & 7;
            cpasync16(su + dstb + sw128((uint32_t)(row*128 + g*16)),
                      src + (size_t)row * HD + half*64 + g*8);
        }
        CP_COMMIT();
    };

    // convert one x chunk (fp32 in stage) -> fp16 A ring slot
    auto convert_x = [&](int chunk) {
        uint32_t xb = su + STG(chunk & 3) + X_OFF;
        uint32_t ab = su + A_RING + (uint32_t)(chunk & 1) * 4096;
        int row = tid >> 2, oct = tid & 3;
        uint32_t so = (uint32_t)(row*128 + oct*32);
        float4 f0 = *(const float4*)(smem + (xb - su) + sw128(so));
        float4 f1 = *(const float4*)(smem + (xb - su) + sw128(so + 16));
        __half2 h0 = __floats2half2_rn(f0.x, f0.y);
        __half2 h1 = __floats2half2_rn(f0.z, f0.w);
        __half2 h2 = __floats2half2_rn(f1.x, f1.y);
        __half2 h3 = __floats2half2_rn(f1.z, f1.w);
        uint4 v = { *(uint32_t*)&h0, *(uint32_t*)&h1, *(uint32_t*)&h2, *(uint32_t*)&h3 };
        *(uint4*)(smem + (ab - su) + sw64((uint32_t)(row*64 + oct*16))) = v;
    };

    // GEMM0 compute for chunk i (single-pass fp16)
    auto compute_g0 = [&](int i) {
        uint32_t ab = su + A_RING + (uint32_t)(i & 1) * 4096;
        uint32_t bb = su + STG(i & 3) + B_OFF;
        #pragma unroll
        for (int ks = 0; ks < 2; ks++) {
            uint32_t af[2][4];
            #pragma unroll
            for (int mi = 0; mi < 2; mi++)
                ldsm4(ab + sw64((uint32_t)(wm*32 + mi*16 + aLane)*64 + (uint32_t)ks*32 + aColSel), af[mi]);
            #pragma unroll
            for (int nn = 0; nn < 2; nn++) {
                uint32_t bf[4];
                ldsm4(bb + sw64((uint32_t)(wn*32 + nn*16 + bRow)*64 + (uint32_t)ks*32 + bColSel), bf);
                #pragma unroll
                for (int mi = 0; mi < 2; mi++) {
                    mma16816(acc[mi][nn*2],   af[mi], bf[0], bf[1]);
                    mma16816(acc[mi][nn*2+1], af[mi], bf[2], bf[3]);
                }
            }
        }
    };
    // GEMM1/2 compute: A = h (256B rows), B = W half buffer (128B rows), 4 ksteps
    auto compute_g12 = [&](uint32_t wbase, uint32_t kbyte) {
        #pragma unroll
        for (int ks = 0; ks < 4; ks++) {
            uint32_t af[2][4];
            #pragma unroll
            for (int mi = 0; mi < 2; mi++)
                ldsm4(su + H_OFF + sw256((uint32_t)(wm*32 + mi*16 + aLane)*256 + kbyte + (uint32_t)ks*32 + aColSel), af[mi]);
            #pragma unroll
            for (int nn = 0; nn < 2; nn++) {
                uint32_t bf[4];
                ldsm4(su + wbase + sw128((uint32_t)(wn*32 + nn*16 + bRow)*128 + (uint32_t)ks*32 + bColSel), bf);
                #pragma unroll
                for (int mi = 0; mi < 2; mi++) {
                    mma16816(acc[mi][nn*2],   af[mi], bf[0], bf[1]);
                    mma16816(acc[mi][nn*2+1], af[mi], bf[2], bf[3]);
                }
            }
        }
    };

    // ---- GEMM0: 4-stage ring, commit 3 ahead, wait_group<=2 ----------------
    cp_chunk(0);
    cp_chunk(1);
    cp_chunk(2);
    CP_WAIT2();
    __syncthreads();          // chunk0 x visible (and biases)
    convert_x(0);
    __syncthreads();          // A(0) visible

    for (int i = 0; i < NCHUNK; i++) {
        if (i + 3 < NCHUNK) cp_chunk(i + 3);
        if (i + 1 < NCHUNK) {
            if      (i + 3 < NCHUNK) CP_WAIT2();
            else if (i + 2 < NCHUNK) CP_WAIT1();
            else                     CP_WAIT0();
            __syncthreads();        // chunk i+1 x arrived everywhere
            convert_x(i + 1);
        }
        compute_g0(i);
        __syncthreads();            // publish A(i+1); retire stage i%4 reads
    }

    // ---- prefetch W1 halves (overlap epilogue 0) ----------------------------
    cp_Whalf(g_W1T, 0, WB0);
    cp_Whalf(g_W1T, 1, WB1);

    // ---- epilogue 0: bias + rmsnorm; h -> smem fp16 (256B rows) -------------
    {
        float ssp[4] = {0.f, 0.f, 0.f, 0.f};   // [mi][half]
        #pragma unroll
        for (int mi = 0; mi < 2; mi++)
            #pragma unroll
            for (int n8 = 0; n8 < 4; n8++) {
                float2 bv = *(float2*)&b0s[wn*32 + n8*8 + colbase];
                float* c = acc[mi][n8];
                c[0] += bv.x; c[1] += bv.y; c[2] += bv.x; c[3] += bv.y;
                ssp[mi*2]   = fmaf(c[0], c[0], fmaf(c[1], c[1], ssp[mi*2]));
                ssp[mi*2+1] = fmaf(c[2], c[2], fmaf(c[3], c[3], ssp[mi*2+1]));
            }
        #pragma unroll
        for (int i = 0; i < 4; i++) {
            ssp[i] += __shfl_xor_sync(0xffffffffu, ssp[i], 1);
            ssp[i] += __shfl_xor_sync(0xffffffffu, ssp[i], 2);
        }
        if ((lane & 3) == 0) {
            #pragma unroll
            for (int i = 0; i < 4; i++) {
                int r = wm*32 + (i >> 1)*16 + (i & 1)*8 + qr;
                part[wn*64 + r] = ssp[i];
            }
        }
        __syncthreads();
        #pragma unroll
        for (int i = 0; i < 4; i++) {
            int r = wm*32 + (i >> 1)*16 + (i & 1)*8 + qr;
            float ss = part[r] + part[64 + r] + part[128 + r] + part[192 + r];
            float sc = rsqrtf(ss * (1.f/128.f) + 1e-6f);
            int mi = i >> 1, half = i & 1;
            #pragma unroll
            for (int n8 = 0; n8 < 4; n8++) {
                float v0 = acc[mi][n8][half*2]     * sc;
                float v1 = acc[mi][n8][half*2 + 1] * sc;
                __half2 h2 = __floats2half2_rn(v0, v1);
                int col = wn*32 + n8*8 + colbase;
                *(uint32_t*)(smem + H_OFF + sw256((uint32_t)(r*256 + col*2))) = *(uint32_t*)&h2;
            }
        }
    }
    CP_WAIT1();               // W1 half0 in
    __syncthreads();          // h + WB0 visible

    // ---- GEMM1 --------------------------------------------------------------
    zero_acc();
    compute_g12(WB0, 0);
    __syncthreads();          // WB0 free
    cp_Whalf(g_W2T, 0, WB0);
    CP_WAIT1();               // W1 half1 in
    __syncthreads();
    compute_g12(WB1, 128);
    __syncthreads();          // WB1 free; h reads done
    cp_Whalf(g_W2T, 1, WB1);

    // ---- epilogue 1: sigmoid + residual; h rewritten in place (thread-local)
    #pragma unroll
    for (int mi = 0; mi < 2; mi++)
        #pragma unroll
        for (int half = 0; half < 2; half++) {
            int r = wm*32 + mi*16 + half*8 + qr;
            #pragma unroll
            for (int n8 = 0; n8 < 4; n8++) {
                int col = wn*32 + n8*8 + colbase;
                float2 bv = *(float2*)&b1s[col];
                uint32_t off = sw256((uint32_t)(r*256 + col*2));
                uint32_t hu = *(uint32_t*)(smem + H_OFF + off);
                __half2 hb = *(__half2*)&hu;
                float r0 = __low2float(hb), r1 = __high2float(hb);
                float v0 = 1.f / (1.f + __expf(-(acc[mi][n8][half*2]     + bv.x))) + r0;
                float v1 = 1.f / (1.f + __expf(-(acc[mi][n8][half*2 + 1] + bv.y))) + r1;
                // keep exact h1 for the final residual in acc? acc is reused; store fp16
                __half2 h2 = __floats2half2_rn(v0, v1);
                *(uint32_t*)(smem + H_OFF + off) = *(uint32_t*)&h2;
            }
        }
    CP_WAIT1();               // W2 half0 in
    __syncthreads();          // h1 + WB0 visible

    // ---- GEMM2 --------------------------------------------------------------
    zero_acc();
    compute_g12(WB0, 0);
    CP_WAIT0();               // W2 half1 in
    __syncthreads();
    compute_g12(WB1, 128);

    // ---- epilogue 2: relu + residual; store ---------------------------------
    #pragma unroll
    for (int mi = 0; mi < 2; mi++)
        #pragma unroll
        for (int half = 0; half < 2; half++) {
            int r = wm*32 + mi*16 + half*8 + qr;
            float* orow = out + (size_t)(m0 + r) * HD;
            #pragma unroll
            for (int n8 = 0; n8 < 4; n8++) {
                int col = wn*32 + n8*8 + colbase;
                float2 bv = *(float2*)&b2s[col];
                uint32_t hu = *(uint32_t*)(smem + H_OFF + sw256((uint32_t)(r*256 + col*2)));
                __half2 hb = *(__half2*)&hu;
                float2 o;
                o.x = fmaxf(acc[mi][n8][half*2]     + bv.x, 0.f) + __low2float(hb);
                o.y = fmaxf(acc[mi][n8][half*2 + 1] + bv.y, 0.f) + __high2float(hb);
                *(float2*)(orow + col) = o;
            }
        }
}

// ---------------- launch ----------------------------------------------------
extern "C" void kernel_launch(void* const* d_in, const int* in_sizes, int n_in,
                              void* d_out, int out_size)
{
    const float* x  = (const float*)d_in[0];
    const float* W0 = (const float*)d_in[1];
    const float* b0 = (const float*)d_in[2];
    const float* W1 = (const float*)d_in[3];
    const float* b1 = (const float*)d_in[4];
    const float* W2 = (const float*)d_in[5];
    const float* b2 = (const float*)d_in[6];
    float* out = (float*)d_out;

    const int M = in_sizes[0] / DIN;   // 32768

    prep_w<<<dim3(DIN/32, HD/32), dim3(32, 8)>>>(W0, DIN, 0);
    prep_w<<<dim3(HD/32,  HD/32), dim3(32, 8)>>>(W1, HD, 1);
    prep_w<<<dim3(HD/32,  HD/32), dim3(32, 8)>>>(W2, HD, 2);

    cudaFuncSetAttribute(fused_mlp_v9,
                         cudaFuncAttributeMaxDynamicSharedMemorySize, SMEM_TOTAL);
    fused_mlp_v9<<<M / BM, THREADS, SMEM_TOTAL>>>(x, b0, b1, b2, out);
}